// round 10
// baseline (speedup 1.0000x reference)
#include <cuda_runtime.h>
#include <cuda_fp16.h>
#include <cstdint>
#include <math.h>

#define NTOK  65536
#define DIN   512
#define DK    256
#define MS    64

// ---------------- static scratch (fp16) ----------------
__device__ __half g_encw_h[DK * DIN];          // enc_w fp16
__device__ __half g_mem_h[MS * DK];            // mem fp16
__device__ __half g_dt_h[MS * DIN];            // Dt fp16

// ======================= helpers =======================
__device__ __forceinline__ uint32_t smem_u32(const void* p) {
    uint32_t a;
    asm("{ .reg .u64 t; cvta.to.shared.u64 t, %1; cvt.u32.u64 %0, t; }"
        : "=r"(a) : "l"(p));
    return a;
}
__device__ __forceinline__ uint32_t pack_h2(float a, float b) {
    __half2 t = __floats2half2_rn(a, b);
    return *reinterpret_cast<uint32_t*>(&t);
}
__device__ __forceinline__ void split2h(float a, float b, uint32_t& hi, uint32_t& lo) {
    __half ha = __float2half_rn(a), hb = __float2half_rn(b);
    __half2 hp; hp.x = ha; hp.y = hb;
    hi = *reinterpret_cast<uint32_t*>(&hp);
    lo = pack_h2(a - __half2float(ha), b - __half2float(hb));
}
__device__ __forceinline__ void split4h(float4 v, unsigned long long& hi,
                                        unsigned long long& lo) {
    uint32_t h0, l0, h1, l1;
    split2h(v.x, v.y, h0, l0);
    split2h(v.z, v.w, h1, l1);
    hi = (unsigned long long)h0 | ((unsigned long long)h1 << 32);
    lo = (unsigned long long)l0 | ((unsigned long long)l1 << 32);
}
__device__ __forceinline__ void sts64(uint32_t addr, unsigned long long v) {
    asm volatile("st.shared.b64 [%0], %1;" :: "r"(addr), "l"(v) : "memory");
}
__device__ __forceinline__ void sts32(uint32_t addr, uint32_t v) {
    asm volatile("st.shared.b32 [%0], %1;" :: "r"(addr), "r"(v) : "memory");
}
__device__ __forceinline__ void cp16(uint32_t saddr, const void* g) {
    asm volatile("cp.async.cg.shared.global [%0], [%1], 16;"
                 :: "r"(saddr), "l"(g) : "memory");
}
#define CP_COMMIT() asm volatile("cp.async.commit_group;" ::: "memory")
#define CP_WAIT(n)  asm volatile("cp.async.wait_group %0;" :: "n"(n) : "memory")

__device__ __forceinline__ void ldsm_x4(uint32_t* r, uint32_t addr) {
    asm volatile("ldmatrix.sync.aligned.m8n8.x4.shared.b16 {%0,%1,%2,%3}, [%4];"
                 : "=r"(r[0]), "=r"(r[1]), "=r"(r[2]), "=r"(r[3]) : "r"(addr));
}
__device__ __forceinline__ void ldsm_x4_t(uint32_t* r, uint32_t addr) {
    asm volatile("ldmatrix.sync.aligned.m8n8.x4.trans.shared.b16 {%0,%1,%2,%3}, [%4];"
                 : "=r"(r[0]), "=r"(r[1]), "=r"(r[2]), "=r"(r[3]) : "r"(addr));
}
__device__ __forceinline__ void mma16816(float* d, const uint32_t* a,
                                         uint32_t b0, uint32_t b1) {
    asm volatile(
        "mma.sync.aligned.m16n8k16.row.col.f32.f16.f16.f32 "
        "{%0,%1,%2,%3}, {%4,%5,%6,%7}, {%8,%9}, {%0,%1,%2,%3};"
        : "+f"(d[0]), "+f"(d[1]), "+f"(d[2]), "+f"(d[3])
        : "r"(a[0]), "r"(a[1]), "r"(a[2]), "r"(a[3]), "r"(b0), "r"(b1));
}

// ---------------- prep 1: enc_w, mem -> fp16 ----------------
__global__ void prep_cvt(const float* __restrict__ ew, const float* __restrict__ mm)
{
    int i = blockIdx.x * blockDim.x + threadIdx.x;
    int st = gridDim.x * blockDim.x;
    for (int j = i; j < DK * DIN; j += st)
        g_encw_h[j] = __float2half_rn(ew[j]);
    for (int j = i; j < MS * DK; j += st)
        g_mem_h[j] = __float2half_rn(mm[j]);
}

// ---------------- prep 2: Dt[s][n] = dec_w[n,:].mem[s,:] -> fp16 ----------------
__global__ void prep_dt(const float* __restrict__ dw, const float* __restrict__ mm)
{
    int s = threadIdx.x & 63;
    int n = blockIdx.x * 4 + (threadIdx.x >> 6);
    const float4* wr = (const float4*)(dw + (size_t)n * DK);
    const float4* mr = (const float4*)(mm + (size_t)s * DK);
    float acc = 0.0f;
#pragma unroll 8
    for (int k = 0; k < DK / 4; k++) {
        float4 a = __ldg(wr + k), b = __ldg(mr + k);
        acc += a.x * b.x + a.y * b.y + a.z * b.z + a.w * b.w;
    }
    g_dt_h[s * DIN + n] = __float2half_rn(acc);
}

// ===========================================================================
// Fully fused kernel: 128 tokens/block, 512 threads, grid 512.
//   Phase E: encode (2 N-halves, K streamed, warp tile 32x32, 2-pass A-split)
//            E = tanh(seq@enc_w^T+b) written to SMEM only (fp16 hi/lo).
//   Phase A (warps 0-7): logits -> softmax -> att out -> memo -> recon.
// SMEM: E region (135168) | chunk region (61440).  mem/Dt overlay after use.
// ===========================================================================
#define EROW   528                         // 256 fp16 + pad (bytes)
#define ESZ    (2 * 128 * EROW)            // 135168  (hi plane | lo plane)
#define RSB    80
#define PART   (128 * RSB)                 // 10240
#define BUFSZ  (3 * PART)                  // seqhi | seqlo | W
#define CHREG  (2 * BUFSZ)                 // 61440
#define DTROW  1040
#define FU_SMEM (ESZ + CHREG)              // 196608

__global__ void __launch_bounds__(512, 1)
fused_all(const float* __restrict__ seq, const float* __restrict__ enc_b,
          float* __restrict__ att_out, float* __restrict__ mem_out,
          float* __restrict__ recon, const float* __restrict__ dec_b)
{
    extern __shared__ char smc[];
    const uint32_t sb  = smem_u32(smc);
    const uint32_t sEhi = sb, sElo = sb + 128 * EROW;
    const uint32_t sCH = sb + ESZ;             // chunk buffers
    const uint32_t sM  = sCH;                  // mem bank (after encode)
    const uint32_t sD  = sb;                   // Dt (after logits, over E)

    const int tid = threadIdx.x, wid = tid >> 5, lane = tid & 31;
    const int wm = wid & 3, wn = wid >> 2;     // encode 4x4 warp grid
    const size_t t0 = (size_t)blockIdx.x * 128;

    const int lrow = tid >> 3, lc4 = tid & 7;
    const int wrow = tid >> 2, wseg = tid & 3;
    const int lr = lane & 15, half = lane >> 4;
    const int tq = lane >> 2, tr = lane & 3;

    // ================= Phase E: encode =================
    float4 av[2];
    auto issue_w = [&](int h, int c, int buf) {
        cp16(sCH + buf * BUFSZ + 2 * PART + wrow * RSB + wseg * 16,
             g_encw_h + (size_t)(h * 128 + wrow) * DIN + c * 32 + wseg * 8);
    };
    auto load_a = [&](int c) {
#pragma unroll
        for (int l = 0; l < 2; l++) {
            int row = lrow + l * 64;
            av[l] = __ldg((const float4*)(seq + (t0 + row) * DIN + c * 32 + lc4 * 4));
        }
    };
    auto store_a = [&](int buf) {
#pragma unroll
        for (int l = 0; l < 2; l++) {
            int row = lrow + l * 64;
            uint32_t off = sCH + buf * BUFSZ + row * RSB + lc4 * 8;
            unsigned long long hi, lo;
            split4h(av[l], hi, lo);
            sts64(off, hi);
            sts64(off + PART, lo);
        }
    };

    for (int h = 0; h < 2; h++) {
        float acc[2][4][4];
#pragma unroll
        for (int i = 0; i < 2; i++)
#pragma unroll
            for (int j = 0; j < 4; j++)
#pragma unroll
                for (int k = 0; k < 4; k++) acc[i][j][k] = 0.0f;

        issue_w(h, 0, 0); CP_COMMIT();
        load_a(0); store_a(0);

        for (int c = 0; c < 16; c++) {
            CP_WAIT(0);
            __syncthreads();
            if (c + 1 < 16) {
                issue_w(h, c + 1, (c + 1) & 1); CP_COMMIT();
                load_a(c + 1);
            }
            // compute chunk c from buffer c&1
            {
                const uint32_t base = sCH + (c & 1) * BUFSZ;
                const uint32_t lh = half * 16;
#pragma unroll
                for (int ks = 0; ks < 2; ks++) {
                    uint32_t ahf[2][4], alf[2][4], whf[2][4];
#pragma unroll
                    for (int mt = 0; mt < 2; mt++) {
                        uint32_t ao = (wm * 32 + mt * 16 + lr) * RSB + ks * 32 + lh;
                        ldsm_x4(ahf[mt], base + ao);
                        ldsm_x4(alf[mt], base + PART + ao);
                    }
#pragma unroll
                    for (int g = 0; g < 2; g++) {
                        uint32_t wo = (wn * 32 + g * 16 + lr) * RSB + ks * 32 + lh;
                        ldsm_x4(whf[g], base + 2 * PART + wo);
                    }
#pragma unroll
                    for (int mt = 0; mt < 2; mt++)
#pragma unroll
                        for (int g = 0; g < 2; g++) {
                            mma16816(acc[mt][2 * g],     ahf[mt], whf[g][0], whf[g][2]);
                            mma16816(acc[mt][2 * g + 1], ahf[mt], whf[g][1], whf[g][3]);
                        }
#pragma unroll
                    for (int mt = 0; mt < 2; mt++)
#pragma unroll
                        for (int g = 0; g < 2; g++) {
                            mma16816(acc[mt][2 * g],     alf[mt], whf[g][0], whf[g][2]);
                            mma16816(acc[mt][2 * g + 1], alf[mt], whf[g][1], whf[g][3]);
                        }
                }
            }
            if (c + 1 < 16) store_a((c + 1) & 1);
        }

        // epilogue: tanh + bias -> E smem (fp16 hi/lo), conflict-free STS
#pragma unroll
        for (int mt = 0; mt < 2; mt++) {
            int row = wm * 32 + mt * 16 + tq;
#pragma unroll
            for (int nt = 0; nt < 4; nt++) {
                int col = h * 128 + wn * 32 + nt * 8 + tr * 2;
                float bx = __ldg(enc_b + col), by = __ldg(enc_b + col + 1);
                float v0 = tanhf(acc[mt][nt][0] + bx), v1 = tanhf(acc[mt][nt][1] + by);
                float v2 = tanhf(acc[mt][nt][2] + bx), v3 = tanhf(acc[mt][nt][3] + by);
                uint32_t hi, lo;
                split2h(v0, v1, hi, lo);
                sts32(sEhi + row * EROW + col * 2, hi);
                sts32(sElo + row * EROW + col * 2, lo);
                split2h(v2, v3, hi, lo);
                sts32(sEhi + (row + 8) * EROW + col * 2, hi);
                sts32(sElo + (row + 8) * EROW + col * 2, lo);
            }
        }
        __syncthreads();    // half done; chunk region reusable
    }

    // load mem bank into chunk region
#pragma unroll
    for (int it = 0; it < 2; it++) {
        int idx = tid + it * 512;
        int row = idx >> 4, c = idx & 15;        // 64 rows x 16 seg (2048 B/row? no)
        // 64 rows x 512B = 2048 cp16: rows 64, 32 segs -> use 2048/512 = 4? recompute:
        // 64 rows * 32 segs = 2048 -> it<4 with 512 threads. (handled below)
        (void)row; (void)c;
    }
    // (corrected mem load: 64 rows x 32 x 16B)
#pragma unroll
    for (int it = 0; it < 4; it++) {
        int idx = tid + it * 512;
        int row = idx >> 5, c = idx & 31;
        cp16(sM + row * EROW + c * 16, g_mem_h + row * DK + c * 8);
    }
    CP_COMMIT();
    CP_WAIT(0);
    __syncthreads();          // E + mem visible

    // ================= Phase A: warps 0-7, 16 tokens each =================
    const int r0 = wid * 16;
    float S[8][4];
#pragma unroll
    for (int i = 0; i < 8; i++)
#pragma unroll
        for (int j = 0; j < 4; j++) S[i][j] = 0.0f;

    if (wid < 8) {
#pragma unroll
        for (int ks = 0; ks < 16; ks++) {
            uint32_t aoff = (r0 + lr) * EROW + ks * 32 + half * 16;
            uint32_t ahf[4], alf[4], bh[4][4];
            ldsm_x4(ahf, sEhi + aoff);
            ldsm_x4(alf, sElo + aoff);
            const int kbyte = ks * 32 + half * 16;
#pragma unroll
            for (int g = 0; g < 4; g++)
                ldsm_x4(bh[g], sM + (g * 16 + lr) * EROW + kbyte);
#pragma unroll
            for (int g = 0; g < 4; g++) {
                mma16816(S[2 * g],     ahf, bh[g][0], bh[g][2]);
                mma16816(S[2 * g + 1], ahf, bh[g][1], bh[g][3]);
            }
#pragma unroll
            for (int g = 0; g < 4; g++) {
                mma16816(S[2 * g],     alf, bh[g][0], bh[g][2]);
                mma16816(S[2 * g + 1], alf, bh[g][1], bh[g][3]);
            }
        }
    }
    __syncthreads();          // E dead

    // prefetch Dt over E region
#pragma unroll
    for (int it = 0; it < 8; it++) {
        int idx = tid + it * 512;
        int row = idx >> 6, c = idx & 63;
        cp16(sD + row * DTROW + c * 16, g_dt_h + row * DIN + c * 8);
    }
    CP_COMMIT();

    uint32_t Ph[4][4], Pl[4][4];
    const size_t ra = t0 + r0 + tq;
    const int lr8 = lane & 7, kh = (lane >> 3) & 1, nh = lane >> 4;

    if (wid < 8) {
        // softmax (register-only)
        float m0 = -1e30f, m1 = -1e30f;
#pragma unroll
        for (int nt = 0; nt < 8; nt++) {
            m0 = fmaxf(m0, fmaxf(S[nt][0], S[nt][1]));
            m1 = fmaxf(m1, fmaxf(S[nt][2], S[nt][3]));
        }
        m0 = fmaxf(m0, __shfl_xor_sync(0xffffffffu, m0, 1));
        m0 = fmaxf(m0, __shfl_xor_sync(0xffffffffu, m0, 2));
        m1 = fmaxf(m1, __shfl_xor_sync(0xffffffffu, m1, 1));
        m1 = fmaxf(m1, __shfl_xor_sync(0xffffffffu, m1, 2));
        float s0 = 0.0f, s1 = 0.0f;
#pragma unroll
        for (int nt = 0; nt < 8; nt++) {
            S[nt][0] = expf((S[nt][0] - m0) * 0.0625f); s0 += S[nt][0];
            S[nt][1] = expf((S[nt][1] - m0) * 0.0625f); s0 += S[nt][1];
            S[nt][2] = expf((S[nt][2] - m1) * 0.0625f); s1 += S[nt][2];
            S[nt][3] = expf((S[nt][3] - m1) * 0.0625f); s1 += S[nt][3];
        }
        s0 += __shfl_xor_sync(0xffffffffu, s0, 1);
        s0 += __shfl_xor_sync(0xffffffffu, s0, 2);
        s1 += __shfl_xor_sync(0xffffffffu, s1, 1);
        s1 += __shfl_xor_sync(0xffffffffu, s1, 2);
        float i0 = 1.0f / s0, i1 = 1.0f / s1;
#pragma unroll
        for (int nt = 0; nt < 8; nt++) {
            S[nt][0] *= i0; S[nt][1] *= i0; S[nt][2] *= i1; S[nt][3] *= i1;
        }

        // repack P into fp16 A-fragments
#pragma unroll
        for (int kt = 0; kt < 4; kt++) {
            split2h(S[2 * kt][0],     S[2 * kt][1],     Ph[kt][0], Pl[kt][0]);
            split2h(S[2 * kt][2],     S[2 * kt][3],     Ph[kt][1], Pl[kt][1]);
            split2h(S[2 * kt + 1][0], S[2 * kt + 1][1], Ph[kt][2], Pl[kt][2]);
            split2h(S[2 * kt + 1][2], S[2 * kt + 1][3], Ph[kt][3], Pl[kt][3]);
        }

        // attention output
#pragma unroll
        for (int nt = 0; nt < 8; nt++) {
            float2 o0, o1;
            o0.x = S[nt][0]; o0.y = S[nt][1];
            o1.x = S[nt][2]; o1.y = S[nt][3];
            *(float2*)(att_out + ra * MS + nt * 8 + tr * 2)       = o0;
            *(float2*)(att_out + (ra + 8) * MS + nt * 8 + tr * 2) = o1;
        }

        // memo = P @ mem (2-pass)
#pragma unroll
        for (int nc = 0; nc < 4; nc++) {
            float acc2[8][4];
#pragma unroll
            for (int i = 0; i < 8; i++)
#pragma unroll
                for (int j = 0; j < 4; j++) acc2[i][j] = 0.0f;
#pragma unroll
            for (int kt = 0; kt < 4; kt++) {
                uint32_t bh[4][4];
#pragma unroll
                for (int g2 = 0; g2 < 4; g2++) {
                    uint32_t boff = (uint32_t)(kt * 16 + kh * 8 + lr8) * EROW +
                                    (nc * 64 + g2 * 16 + nh * 8) * 2;
                    ldsm_x4_t(bh[g2], sM + boff);
                }
#pragma unroll
                for (int g2 = 0; g2 < 4; g2++) {
                    mma16816(acc2[2 * g2],     Ph[kt], bh[g2][0], bh[g2][1]);
                    mma16816(acc2[2 * g2 + 1], Ph[kt], bh[g2][2], bh[g2][3]);
                }
#pragma unroll
                for (int g2 = 0; g2 < 4; g2++) {
                    mma16816(acc2[2 * g2],     Pl[kt], bh[g2][0], bh[g2][1]);
                    mma16816(acc2[2 * g2 + 1], Pl[kt], bh[g2][2], bh[g2][3]);
                }
            }
#pragma unroll
            for (int nt2 = 0; nt2 < 8; nt2++) {
                int gc = nc * 64 + nt2 * 8 + tr * 2;
                float2 o0, o1;
                o0.x = acc2[nt2][0]; o0.y = acc2[nt2][1];
                o1.x = acc2[nt2][2]; o1.y = acc2[nt2][3];
                *(float2*)(mem_out + ra * DK + gc)       = o0;
                *(float2*)(mem_out + (ra + 8) * DK + gc) = o1;
            }
        }
    }

    CP_WAIT(0);
    __syncthreads();          // Dt visible

    if (wid < 8) {
        // recon = P @ Dt + dec_b (2-pass)
#pragma unroll
        for (int nc = 0; nc < 8; nc++) {
            float acc2[8][4];
#pragma unroll
            for (int i = 0; i < 8; i++)
#pragma unroll
                for (int j = 0; j < 4; j++) acc2[i][j] = 0.0f;
#pragma unroll
            for (int kt = 0; kt < 4; kt++) {
                uint32_t bh[4][4];
#pragma unroll
                for (int g2 = 0; g2 < 4; g2++) {
                    uint32_t boff = (uint32_t)(kt * 16 + kh * 8 + lr8) * DTROW +
                                    (nc * 64 + g2 * 16 + nh * 8) * 2;
                    ldsm_x4_t(bh[g2], sD + boff);
                }
#pragma unroll
                for (int g2 = 0; g2 < 4; g2++) {
                    mma16816(acc2[2 * g2],     Ph[kt], bh[g2][0], bh[g2][1]);
                    mma16816(acc2[2 * g2 + 1], Ph[kt], bh[g2][2], bh[g2][3]);
                }
#pragma unroll
                for (int g2 = 0; g2 < 4; g2++) {
                    mma16816(acc2[2 * g2],     Pl[kt], bh[g2][0], bh[g2][1]);
                    mma16816(acc2[2 * g2 + 1], Pl[kt], bh[g2][2], bh[g2][3]);
                }
            }
#pragma unroll
            for (int nt2 = 0; nt2 < 8; nt2++) {
                int gc = nc * 64 + nt2 * 8 + tr * 2;
                float2 b2 = *(const float2*)(dec_b + gc);
                float2 o0, o1;
                o0.x = acc2[nt2][0] + b2.x; o0.y = acc2[nt2][1] + b2.y;
                o1.x = acc2[nt2][2] + b2.x; o1.y = acc2[nt2][3] + b2.y;
                *(float2*)(recon + ra * DIN + gc)       = o0;
                *(float2*)(recon + (ra + 8) * DIN + gc) = o1;
            }
        }
    }
}

// ---------------------------------------------------------------------------
extern "C" void kernel_launch(void* const* d_in, const int* in_sizes, int n_in,
                              void* d_out, int out_size)
{
    const float* seq   = (const float*)d_in[0];
    const float* enc_w = (const float*)d_in[1];
    const float* enc_b = (const float*)d_in[2];
    const float* mem   = (const float*)d_in[3];
    const float* dec_w = (const float*)d_in[4];
    const float* dec_b = (const float*)d_in[5];

    float* recon = (float*)d_out;
    float* att   = recon + (size_t)NTOK * DIN;
    float* memo  = att   + (size_t)NTOK * MS;

    cudaFuncSetAttribute(fused_all,
                         cudaFuncAttributeMaxDynamicSharedMemorySize, FU_SMEM);

    prep_cvt<<<160, 256>>>(enc_w, mem);
    prep_dt<<<DIN / 4, 256>>>(dec_w, mem);

    fused_all<<<NTOK / 128, 512, FU_SMEM>>>(seq, enc_b, att, memo, recon, dec_b);
}

// round 11
// speedup vs baseline: 1.0635x; 1.0635x over previous
#include <cuda_runtime.h>
#include <cuda_fp16.h>
#include <cstdint>
#include <math.h>

#define NTOK  65536
#define DIN   512
#define DK    256
#define MS    64

// ---------------- static scratch (fp16) ----------------
__device__ __half g_encw_h[DK * DIN];
__device__ __half g_mem_h[MS * DK];
__device__ __half g_dt_h[MS * DIN];
__device__ __half g_enc_hi[(size_t)NTOK * DK], g_enc_lo[(size_t)NTOK * DK];

// ======================= helpers =======================
__device__ __forceinline__ uint32_t smem_u32(const void* p) {
    uint32_t a;
    asm("{ .reg .u64 t; cvta.to.shared.u64 t, %1; cvt.u32.u64 %0, t; }"
        : "=r"(a) : "l"(p));
    return a;
}
__device__ __forceinline__ uint32_t pack_h2(float a, float b) {
    __half2 t = __floats2half2_rn(a, b);
    return *reinterpret_cast<uint32_t*>(&t);
}
__device__ __forceinline__ void split2h(float a, float b, uint32_t& hi, uint32_t& lo) {
    __half ha = __float2half_rn(a), hb = __float2half_rn(b);
    __half2 hp; hp.x = ha; hp.y = hb;
    hi = *reinterpret_cast<uint32_t*>(&hp);
    lo = pack_h2(a - __half2float(ha), b - __half2float(hb));
}
__device__ __forceinline__ void split4h(float4 v, unsigned long long& hi,
                                        unsigned long long& lo) {
    uint32_t h0, l0, h1, l1;
    split2h(v.x, v.y, h0, l0);
    split2h(v.z, v.w, h1, l1);
    hi = (unsigned long long)h0 | ((unsigned long long)h1 << 32);
    lo = (unsigned long long)l0 | ((unsigned long long)l1 << 32);
}
__device__ __forceinline__ void sts64(uint32_t addr, unsigned long long v) {
    asm volatile("st.shared.b64 [%0], %1;" :: "r"(addr), "l"(v) : "memory");
}
__device__ __forceinline__ void cp16(uint32_t saddr, const void* g) {
    asm volatile("cp.async.cg.shared.global [%0], [%1], 16;"
                 :: "r"(saddr), "l"(g) : "memory");
}
#define CP_COMMIT() asm volatile("cp.async.commit_group;" ::: "memory")
#define CP_WAIT(n)  asm volatile("cp.async.wait_group %0;" :: "n"(n) : "memory")

__device__ __forceinline__ void ldsm_x4(uint32_t* r, uint32_t addr) {
    asm volatile("ldmatrix.sync.aligned.m8n8.x4.shared.b16 {%0,%1,%2,%3}, [%4];"
                 : "=r"(r[0]), "=r"(r[1]), "=r"(r[2]), "=r"(r[3]) : "r"(addr));
}
__device__ __forceinline__ void ldsm_x4_t(uint32_t* r, uint32_t addr) {
    asm volatile("ldmatrix.sync.aligned.m8n8.x4.trans.shared.b16 {%0,%1,%2,%3}, [%4];"
                 : "=r"(r[0]), "=r"(r[1]), "=r"(r[2]), "=r"(r[3]) : "r"(addr));
}
__device__ __forceinline__ void mma16816(float* d, const uint32_t* a,
                                         uint32_t b0, uint32_t b1) {
    asm volatile(
        "mma.sync.aligned.m16n8k16.row.col.f32.f16.f16.f32 "
        "{%0,%1,%2,%3}, {%4,%5,%6,%7}, {%8,%9}, {%0,%1,%2,%3};"
        : "+f"(d[0]), "+f"(d[1]), "+f"(d[2]), "+f"(d[3])
        : "r"(a[0]), "r"(a[1]), "r"(a[2]), "r"(a[3]), "r"(b0), "r"(b1));
}

// ---------------- prep 1: enc_w, mem -> fp16 (1 float2/thread) ----------------
__global__ void prep_cvt(const float* __restrict__ ew, const float* __restrict__ mm)
{
    int i = blockIdx.x * blockDim.x + threadIdx.x;   // 65536 threads
    {
        float2 v = __ldg((const float2*)ew + i);
        *((uint32_t*)g_encw_h + i) = pack_h2(v.x, v.y);
    }
    if (i < MS * DK / 2) {
        float2 v = __ldg((const float2*)mm + i);
        *((uint32_t*)g_mem_h + i) = pack_h2(v.x, v.y);
    }
}

// ---------------- prep 2: Dt[s][n] = dec_w[n,:].mem[s,:] -> fp16 ----------------
__global__ void prep_dt(const float* __restrict__ dw, const float* __restrict__ mm)
{
    int s = threadIdx.x & 63;
    int n = blockIdx.x * 4 + (threadIdx.x >> 6);
    const float4* wr = (const float4*)(dw + (size_t)n * DK);
    const float4* mr = (const float4*)(mm + (size_t)s * DK);
    float acc = 0.0f;
#pragma unroll 8
    for (int k = 0; k < DK / 4; k++) {
        float4 a = __ldg(wr + k), b = __ldg(mr + k);
        acc += a.x * b.x + a.y * b.y + a.z * b.z + a.w * b.w;
    }
    g_dt_h[s * DIN + n] = __float2half_rn(acc);
}

// ===========================================================================
// Encode GEMM: BM=128, BN=256 (full width), BK=32, 512 threads.
// Warp grid 4(M)x4(N), warp tile 32x64. A split fp16 hi/lo; W single fp16.
// seq read exactly once.
// ===========================================================================
#define RSB    80
#define APART  (128 * RSB)                 // 10240 per A plane
#define WPART  (256 * RSB)                 // 20480 for W
#define BUFSZ  (2 * APART + WPART)         // 40960
#define GEMM_SMEM (2 * BUFSZ)              // 81920

__global__ void __launch_bounds__(512, 1)
enc_gemm(const float* __restrict__ A32, const float* __restrict__ bias)
{
    extern __shared__ char smc[];
    const uint32_t sb = smem_u32(smc);
    const int tid = threadIdx.x, wid = tid >> 5, lane = tid & 31;
    const int wm = wid & 3, wn = wid >> 2;     // 4x4, warp tile 32(M) x 64(N)
    const int NCH = DIN / 32;                  // 16

    const size_t arow0 = (size_t)blockIdx.x * 128;

    const int lrow = tid >> 3, lc4 = tid & 7;      // A: 2 float4/thread
    const int wrow2 = tid >> 2, wseg = tid & 3;    // W: 2 cp16/thread (rows +0,+128)

    float acc[2][8][4];
#pragma unroll
    for (int i = 0; i < 2; i++)
#pragma unroll
        for (int j = 0; j < 8; j++)
#pragma unroll
            for (int k = 0; k < 4; k++) acc[i][j][k] = 0.0f;

    float4 av[2];

    auto issue_w = [&](int c, int buf) {
        const uint32_t base = sb + buf * BUFSZ + 2 * APART;
#pragma unroll
        for (int l = 0; l < 2; l++) {
            int row = wrow2 + l * 128;
            cp16(base + row * RSB + wseg * 16,
                 g_encw_h + (size_t)row * DIN + c * 32 + wseg * 8);
        }
    };
    auto load_a = [&](int c) {
#pragma unroll
        for (int l = 0; l < 2; l++) {
            int row = lrow + l * 64;
            av[l] = __ldg((const float4*)(A32 + (arow0 + row) * DIN + c * 32 + lc4 * 4));
        }
    };
    auto store_a = [&](int buf) {
        const uint32_t base = sb + buf * BUFSZ;
#pragma unroll
        for (int l = 0; l < 2; l++) {
            int row = lrow + l * 64;
            uint32_t off = row * RSB + lc4 * 8;
            unsigned long long hi, lo;
            split4h(av[l], hi, lo);
            sts64(base + off, hi);
            sts64(base + APART + off, lo);
        }
    };
    auto compute = [&](int buf) {
        const uint32_t base = sb + buf * BUFSZ;
        const uint32_t lr = lane & 15, lh = (lane >> 4) * 16;
#pragma unroll
        for (int ks = 0; ks < 2; ks++) {
            uint32_t ahf[2][4], alf[2][4], whf[4][4];
#pragma unroll
            for (int mt = 0; mt < 2; mt++) {
                uint32_t ao = (wm * 32 + mt * 16 + lr) * RSB + ks * 32 + lh;
                ldsm_x4(ahf[mt], base + ao);
                ldsm_x4(alf[mt], base + APART + ao);
            }
#pragma unroll
            for (int g = 0; g < 4; g++) {
                uint32_t wo = (wn * 64 + g * 16 + lr) * RSB + ks * 32 + lh;
                ldsm_x4(whf[g], base + 2 * APART + wo);
            }
            // pass 1: A_hi x W
#pragma unroll
            for (int mt = 0; mt < 2; mt++)
#pragma unroll
                for (int g = 0; g < 4; g++) {
                    mma16816(acc[mt][2 * g],     ahf[mt], whf[g][0], whf[g][2]);
                    mma16816(acc[mt][2 * g + 1], ahf[mt], whf[g][1], whf[g][3]);
                }
            // pass 2: A_lo x W
#pragma unroll
            for (int mt = 0; mt < 2; mt++)
#pragma unroll
                for (int g = 0; g < 4; g++) {
                    mma16816(acc[mt][2 * g],     alf[mt], whf[g][0], whf[g][2]);
                    mma16816(acc[mt][2 * g + 1], alf[mt], whf[g][1], whf[g][3]);
                }
        }
    };

    issue_w(0, 0); CP_COMMIT();
    load_a(0); store_a(0);

    for (int c = 0; c < NCH; c++) {
        CP_WAIT(0);
        __syncthreads();
        if (c + 1 < NCH) {
            issue_w(c + 1, (c + 1) & 1); CP_COMMIT();
            load_a(c + 1);
        }
        compute(c & 1);
        if (c + 1 < NCH) store_a((c + 1) & 1);
    }

    // epilogue: tanh -> fp16 hi/lo
    const int tq = lane >> 2, tr = lane & 3;
#pragma unroll
    for (int mt = 0; mt < 2; mt++) {
        size_t r0 = arow0 + wm * 32 + mt * 16 + tq;
#pragma unroll
        for (int nt = 0; nt < 8; nt++) {
            int gn = wn * 64 + nt * 8 + tr * 2;
            float bx = __ldg(bias + gn), by = __ldg(bias + gn + 1);
            float v0 = tanhf(acc[mt][nt][0] + bx), v1 = tanhf(acc[mt][nt][1] + by);
            float v2 = tanhf(acc[mt][nt][2] + bx), v3 = tanhf(acc[mt][nt][3] + by);
            uint32_t h, l;
            split2h(v0, v1, h, l);
            *(uint32_t*)(g_enc_hi + r0 * DK + gn) = h;
            *(uint32_t*)(g_enc_lo + r0 * DK + gn) = l;
            split2h(v2, v3, h, l);
            *(uint32_t*)(g_enc_hi + (r0 + 8) * DK + gn) = h;
            *(uint32_t*)(g_enc_lo + (r0 + 8) * DK + gn) = l;
        }
    }
}

// ===========================================================================
// Fused attention + decode (identical to R9): 256 tokens/block, 512 threads.
// ===========================================================================
#define EROW   528
#define ECROW  144
#define DTROW  1040
#define MEMSZ  (64 * EROW)
#define ECBUF  (2 * 256 * ECROW)
#define AT_SMEM (MEMSZ + 2 * ECBUF)

__global__ void __launch_bounds__(512, 1)
attn_fused(float* __restrict__ att_out, float* __restrict__ mem_out,
           float* __restrict__ recon, const float* __restrict__ dec_b)
{
    extern __shared__ char smc[];
    const uint32_t sb = smem_u32(smc);
    const uint32_t sM = sb;
    const uint32_t sE0 = sb + MEMSZ;
    const uint32_t sD = sE0;

    const int tid = threadIdx.x, wid = tid >> 5, lane = tid & 31;
    const size_t t0 = (size_t)blockIdx.x * 256;

    auto issue_mem = [&]() {
#pragma unroll
        for (int it = 0; it < 4; it++) {
            int idx = tid + it * 512;
            int row = idx >> 5, c = idx & 31;
            cp16(sM + row * EROW + c * 16, g_mem_h + row * DK + c * 8);
        }
    };
    auto issue_e = [&](int kc, int buf) {
        const uint32_t base = sE0 + buf * ECBUF;
#pragma unroll
        for (int it = 0; it < 4; it++) {
            int idx = tid + it * 512;
            int row = idx >> 3, seg = idx & 7;
            const size_t go = (t0 + row) * DK + kc * 64 + seg * 8;
            cp16(base + row * ECROW + seg * 16, g_enc_hi + go);
            cp16(base + 256 * ECROW + row * ECROW + seg * 16, g_enc_lo + go);
        }
    };

    issue_mem();
    issue_e(0, 0);
    CP_COMMIT();

    const int lr = lane & 15, half = lane >> 4;
    const int tq = lane >> 2, tr = lane & 3;
    const int r0 = wid * 16;

    float S[8][4];
#pragma unroll
    for (int i = 0; i < 8; i++)
#pragma unroll
        for (int j = 0; j < 4; j++) S[i][j] = 0.0f;

    for (int kc = 0; kc < 4; kc++) {
        CP_WAIT(0);
        __syncthreads();
        if (kc < 3) { issue_e(kc + 1, (kc + 1) & 1); CP_COMMIT(); }
        const uint32_t eb = sE0 + (kc & 1) * ECBUF;
#pragma unroll
        for (int ks = 0; ks < 4; ks++) {
            uint32_t aoff = (r0 + lr) * ECROW + ks * 32 + half * 16;
            uint32_t ahf[4], alf[4], bh[4][4];
            ldsm_x4(ahf, eb + aoff);
            ldsm_x4(alf, eb + 256 * ECROW + aoff);
            const int kbyte = (kc * 4 + ks) * 32 + half * 16;
#pragma unroll
            for (int g = 0; g < 4; g++)
                ldsm_x4(bh[g], sM + (g * 16 + lr) * EROW + kbyte);
#pragma unroll
            for (int g = 0; g < 4; g++) {
                mma16816(S[2 * g],     ahf, bh[g][0], bh[g][2]);
                mma16816(S[2 * g + 1], ahf, bh[g][1], bh[g][3]);
            }
#pragma unroll
            for (int g = 0; g < 4; g++) {
                mma16816(S[2 * g],     alf, bh[g][0], bh[g][2]);
                mma16816(S[2 * g + 1], alf, bh[g][1], bh[g][3]);
            }
        }
    }

    __syncthreads();

#pragma unroll
    for (int it = 0; it < 8; it++) {
        int idx = tid + it * 512;
        int row = idx >> 6, c = idx & 63;
        cp16(sD + row * DTROW + c * 16, g_dt_h + row * DIN + c * 8);
    }
    CP_COMMIT();

    // softmax (register-only)
    float m0 = -1e30f, m1 = -1e30f;
#pragma unroll
    for (int nt = 0; nt < 8; nt++) {
        m0 = fmaxf(m0, fmaxf(S[nt][0], S[nt][1]));
        m1 = fmaxf(m1, fmaxf(S[nt][2], S[nt][3]));
    }
    m0 = fmaxf(m0, __shfl_xor_sync(0xffffffffu, m0, 1));
    m0 = fmaxf(m0, __shfl_xor_sync(0xffffffffu, m0, 2));
    m1 = fmaxf(m1, __shfl_xor_sync(0xffffffffu, m1, 1));
    m1 = fmaxf(m1, __shfl_xor_sync(0xffffffffu, m1, 2));
    float s0 = 0.0f, s1 = 0.0f;
#pragma unroll
    for (int nt = 0; nt < 8; nt++) {
        S[nt][0] = expf((S[nt][0] - m0) * 0.0625f); s0 += S[nt][0];
        S[nt][1] = expf((S[nt][1] - m0) * 0.0625f); s0 += S[nt][1];
        S[nt][2] = expf((S[nt][2] - m1) * 0.0625f); s1 += S[nt][2];
        S[nt][3] = expf((S[nt][3] - m1) * 0.0625f); s1 += S[nt][3];
    }
    s0 += __shfl_xor_sync(0xffffffffu, s0, 1);
    s0 += __shfl_xor_sync(0xffffffffu, s0, 2);
    s1 += __shfl_xor_sync(0xffffffffu, s1, 1);
    s1 += __shfl_xor_sync(0xffffffffu, s1, 2);
    float i0 = 1.0f / s0, i1 = 1.0f / s1;
#pragma unroll
    for (int nt = 0; nt < 8; nt++) {
        S[nt][0] *= i0; S[nt][1] *= i0; S[nt][2] *= i1; S[nt][3] *= i1;
    }

    uint32_t Ph[4][4], Pl[4][4];
#pragma unroll
    for (int kt = 0; kt < 4; kt++) {
        split2h(S[2 * kt][0],     S[2 * kt][1],     Ph[kt][0], Pl[kt][0]);
        split2h(S[2 * kt][2],     S[2 * kt][3],     Ph[kt][1], Pl[kt][1]);
        split2h(S[2 * kt + 1][0], S[2 * kt + 1][1], Ph[kt][2], Pl[kt][2]);
        split2h(S[2 * kt + 1][2], S[2 * kt + 1][3], Ph[kt][3], Pl[kt][3]);
    }

    const size_t ra = t0 + r0 + tq;
#pragma unroll
    for (int nt = 0; nt < 8; nt++) {
        float2 o0, o1;
        o0.x = S[nt][0]; o0.y = S[nt][1];
        o1.x = S[nt][2]; o1.y = S[nt][3];
        *(float2*)(att_out + ra * MS + nt * 8 + tr * 2)       = o0;
        *(float2*)(att_out + (ra + 8) * MS + nt * 8 + tr * 2) = o1;
    }

    // memo = P @ mem (2-pass)
    const int lr8 = lane & 7, kh = (lane >> 3) & 1, nh = lane >> 4;
#pragma unroll
    for (int nc = 0; nc < 4; nc++) {
        float acc2[8][4];
#pragma unroll
        for (int i = 0; i < 8; i++)
#pragma unroll
            for (int j = 0; j < 4; j++) acc2[i][j] = 0.0f;
#pragma unroll
        for (int kt = 0; kt < 4; kt++) {
            uint32_t bh[4][4];
#pragma unroll
            for (int g2 = 0; g2 < 4; g2++) {
                uint32_t boff = (uint32_t)(kt * 16 + kh * 8 + lr8) * EROW +
                                (nc * 64 + g2 * 16 + nh * 8) * 2;
                ldsm_x4_t(bh[g2], sM + boff);
            }
#pragma unroll
            for (int g2 = 0; g2 < 4; g2++) {
                mma16816(acc2[2 * g2],     Ph[kt], bh[g2][0], bh[g2][1]);
                mma16816(acc2[2 * g2 + 1], Ph[kt], bh[g2][2], bh[g2][3]);
            }
#pragma unroll
            for (int g2 = 0; g2 < 4; g2++) {
                mma16816(acc2[2 * g2],     Pl[kt], bh[g2][0], bh[g2][1]);
                mma16816(acc2[2 * g2 + 1], Pl[kt], bh[g2][2], bh[g2][3]);
            }
        }
#pragma unroll
        for (int nt2 = 0; nt2 < 8; nt2++) {
            int gc = nc * 64 + nt2 * 8 + tr * 2;
            float2 o0, o1;
            o0.x = acc2[nt2][0]; o0.y = acc2[nt2][1];
            o1.x = acc2[nt2][2]; o1.y = acc2[nt2][3];
            *(float2*)(mem_out + ra * DK + gc)       = o0;
            *(float2*)(mem_out + (ra + 8) * DK + gc) = o1;
        }
    }

    CP_WAIT(0);
    __syncthreads();

    // recon = P @ Dt + dec_b (2-pass)
#pragma unroll
    for (int nc = 0; nc < 8; nc++) {
        float acc2[8][4];
#pragma unroll
        for (int i = 0; i < 8; i++)
#pragma unroll
            for (int j = 0; j < 4; j++) acc2[i][j] = 0.0f;
#pragma unroll
        for (int kt = 0; kt < 4; kt++) {
            uint32_t bh[4][4];
#pragma unroll
            for (int g2 = 0; g2 < 4; g2++) {
                uint32_t boff = (uint32_t)(kt * 16 + kh * 8 + lr8) * DTROW +
                                (nc * 64 + g2 * 16 + nh * 8) * 2;
                ldsm_x4_t(bh[g2], sD + boff);
            }
#pragma unroll
            for (int g2 = 0; g2 < 4; g2++) {
                mma16816(acc2[2 * g2],     Ph[kt], bh[g2][0], bh[g2][1]);
                mma16816(acc2[2 * g2 + 1], Ph[kt], bh[g2][2], bh[g2][3]);
            }
#pragma unroll
            for (int g2 = 0; g2 < 4; g2++) {
                mma16816(acc2[2 * g2],     Pl[kt], bh[g2][0], bh[g2][1]);
                mma16816(acc2[2 * g2 + 1], Pl[kt], bh[g2][2], bh[g2][3]);
            }
        }
#pragma unroll
        for (int nt2 = 0; nt2 < 8; nt2++) {
            int gc = nc * 64 + nt2 * 8 + tr * 2;
            float2 b2 = *(const float2*)(dec_b + gc);
            float2 o0, o1;
            o0.x = acc2[nt2][0] + b2.x; o0.y = acc2[nt2][1] + b2.y;
            o1.x = acc2[nt2][2] + b2.x; o1.y = acc2[nt2][3] + b2.y;
            *(float2*)(recon + ra * DIN + gc)       = o0;
            *(float2*)(recon + (ra + 8) * DIN + gc) = o1;
        }
    }
}

// ---------------------------------------------------------------------------
extern "C" void kernel_launch(void* const* d_in, const int* in_sizes, int n_in,
                              void* d_out, int out_size)
{
    const float* seq   = (const float*)d_in[0];
    const float* enc_w = (const float*)d_in[1];
    const float* enc_b = (const float*)d_in[2];
    const float* mem   = (const float*)d_in[3];
    const float* dec_w = (const float*)d_in[4];
    const float* dec_b = (const float*)d_in[5];

    float* recon = (float*)d_out;
    float* att   = recon + (size_t)NTOK * DIN;
    float* memo  = att   + (size_t)NTOK * MS;

    cudaFuncSetAttribute(enc_gemm,
                         cudaFuncAttributeMaxDynamicSharedMemorySize, GEMM_SMEM);
    cudaFuncSetAttribute(attn_fused,
                         cudaFuncAttributeMaxDynamicSharedMemorySize, AT_SMEM);

    prep_cvt<<<DK * DIN / 2 / 256, 256>>>(enc_w, mem);   // 256 blocks x 256
    prep_dt<<<DIN / 4, 256>>>(dec_w, mem);

    enc_gemm<<<NTOK / 128, 512, GEMM_SMEM>>>(seq, enc_b);

    attn_fused<<<NTOK / 256, 512, AT_SMEM>>>(att, memo, recon, dec_b);
}

// round 12
// speedup vs baseline: 1.4367x; 1.3509x over previous
#include <cuda_runtime.h>
#include <cuda_fp16.h>
#include <cstdint>
#include <math.h>

#define NTOK  65536
#define DIN   512
#define DK    256
#define MS    64

// ---------------- static scratch (fp16) ----------------
__device__ __half g_encw_h[DK * DIN];
__device__ __half g_mem_h[MS * DK];
__device__ __half g_dt_h[MS * DIN];
__device__ __half g_enc_h[(size_t)NTOK * DK];      // single-plane encoded

// ======================= helpers =======================
__device__ __forceinline__ uint32_t smem_u32(const void* p) {
    uint32_t a;
    asm("{ .reg .u64 t; cvta.to.shared.u64 t, %1; cvt.u32.u64 %0, t; }"
        : "=r"(a) : "l"(p));
    return a;
}
__device__ __forceinline__ uint32_t pack_h2(float a, float b) {
    __half2 t = __floats2half2_rn(a, b);
    return *reinterpret_cast<uint32_t*>(&t);
}
__device__ __forceinline__ void split2h(float a, float b, uint32_t& hi, uint32_t& lo) {
    __half ha = __float2half_rn(a), hb = __float2half_rn(b);
    __half2 hp; hp.x = ha; hp.y = hb;
    hi = *reinterpret_cast<uint32_t*>(&hp);
    lo = pack_h2(a - __half2float(ha), b - __half2float(hb));
}
__device__ __forceinline__ void sts64(uint32_t addr, unsigned long long v) {
    asm volatile("st.shared.b64 [%0], %1;" :: "r"(addr), "l"(v) : "memory");
}
__device__ __forceinline__ void cp16(uint32_t saddr, const void* g) {
    asm volatile("cp.async.cg.shared.global [%0], [%1], 16;"
                 :: "r"(saddr), "l"(g) : "memory");
}
#define CP_COMMIT() asm volatile("cp.async.commit_group;" ::: "memory")
#define CP_WAIT(n)  asm volatile("cp.async.wait_group %0;" :: "n"(n) : "memory")

__device__ __forceinline__ void ldsm_x4(uint32_t* r, uint32_t addr) {
    asm volatile("ldmatrix.sync.aligned.m8n8.x4.shared.b16 {%0,%1,%2,%3}, [%4];"
                 : "=r"(r[0]), "=r"(r[1]), "=r"(r[2]), "=r"(r[3]) : "r"(addr));
}
__device__ __forceinline__ void ldsm_x4_t(uint32_t* r, uint32_t addr) {
    asm volatile("ldmatrix.sync.aligned.m8n8.x4.trans.shared.b16 {%0,%1,%2,%3}, [%4];"
                 : "=r"(r[0]), "=r"(r[1]), "=r"(r[2]), "=r"(r[3]) : "r"(addr));
}
__device__ __forceinline__ void mma16816(float* d, const uint32_t* a,
                                         uint32_t b0, uint32_t b1) {
    asm volatile(
        "mma.sync.aligned.m16n8k16.row.col.f32.f16.f16.f32 "
        "{%0,%1,%2,%3}, {%4,%5,%6,%7}, {%8,%9}, {%0,%1,%2,%3};"
        : "+f"(d[0]), "+f"(d[1]), "+f"(d[2]), "+f"(d[3])
        : "r"(a[0]), "r"(a[1]), "r"(a[2]), "r"(a[3]), "r"(b0), "r"(b1));
}
__device__ __forceinline__ void stcs2(float* p, float2 v) {
    asm volatile("st.global.cs.v2.f32 [%0], {%1,%2};" :: "l"(p), "f"(v.x), "f"(v.y)
                 : "memory");
}

// ---------------- prep 1: enc_w, mem -> fp16 ----------------
__global__ void prep_cvt(const float* __restrict__ ew, const float* __restrict__ mm)
{
    int i = blockIdx.x * blockDim.x + threadIdx.x;   // 65536 threads
    {
        float2 v = __ldg((const float2*)ew + i);
        *((uint32_t*)g_encw_h + i) = pack_h2(v.x, v.y);
    }
    if (i < MS * DK / 2) {
        float2 v = __ldg((const float2*)mm + i);
        *((uint32_t*)g_mem_h + i) = pack_h2(v.x, v.y);
    }
}

// ---------------- prep 2: Dt[s][n] = dec_w[n,:].mem[s,:] -> fp16 ----------------
__global__ void prep_dt(const float* __restrict__ dw, const float* __restrict__ mm)
{
    int s = threadIdx.x & 63;
    int n = blockIdx.x * 4 + (threadIdx.x >> 6);
    const float4* wr = (const float4*)(dw + (size_t)n * DK);
    const float4* mr = (const float4*)(mm + (size_t)s * DK);
    float acc = 0.0f;
#pragma unroll 8
    for (int k = 0; k < DK / 4; k++) {
        float4 a = __ldg(wr + k), b = __ldg(mr + k);
        acc += a.x * b.x + a.y * b.y + a.z * b.z + a.w * b.w;
    }
    g_dt_h[s * DIN + n] = __float2half_rn(acc);
}

// ===========================================================================
// Encode GEMM: BM=128, BN=256, BK=32, 512 threads. Single fp16, 1-pass MMA.
// ===========================================================================
#define RSB    80
#define APART  (128 * RSB)                 // 10240
#define WPART  (256 * RSB)                 // 20480
#define BUFSZ  (APART + WPART)             // 30720
#define GEMM_SMEM (2 * BUFSZ)              // 61440

__global__ void __launch_bounds__(512, 1)
enc_gemm(const float* __restrict__ A32, const float* __restrict__ bias)
{
    extern __shared__ char smc[];
    const uint32_t sb = smem_u32(smc);
    const int tid = threadIdx.x, wid = tid >> 5, lane = tid & 31;
    const int wm = wid & 3, wn = wid >> 2;     // warp tile 32(M) x 64(N)
    const int NCH = DIN / 32;                  // 16

    const size_t arow0 = (size_t)blockIdx.x * 128;

    const int lrow = tid >> 3, lc4 = tid & 7;
    const int wrow2 = tid >> 2, wseg = tid & 3;

    float acc[2][8][4];
#pragma unroll
    for (int i = 0; i < 2; i++)
#pragma unroll
        for (int j = 0; j < 8; j++)
#pragma unroll
            for (int k = 0; k < 4; k++) acc[i][j][k] = 0.0f;

    float4 av[2];

    auto issue_w = [&](int c, int buf) {
        const uint32_t base = sb + buf * BUFSZ + APART;
#pragma unroll
        for (int l = 0; l < 2; l++) {
            int row = wrow2 + l * 128;
            cp16(base + row * RSB + wseg * 16,
                 g_encw_h + (size_t)row * DIN + c * 32 + wseg * 8);
        }
    };
    auto load_a = [&](int c) {
#pragma unroll
        for (int l = 0; l < 2; l++) {
            int row = lrow + l * 64;
            av[l] = __ldg((const float4*)(A32 + (arow0 + row) * DIN + c * 32 + lc4 * 4));
        }
    };
    auto store_a = [&](int buf) {
        const uint32_t base = sb + buf * BUFSZ;
#pragma unroll
        for (int l = 0; l < 2; l++) {
            int row = lrow + l * 64;
            unsigned long long h =
                (unsigned long long)pack_h2(av[l].x, av[l].y) |
                ((unsigned long long)pack_h2(av[l].z, av[l].w) << 32);
            sts64(base + row * RSB + lc4 * 8, h);
        }
    };
    auto compute = [&](int buf) {
        const uint32_t base = sb + buf * BUFSZ;
        const uint32_t lr = lane & 15, lh = (lane >> 4) * 16;
#pragma unroll
        for (int ks = 0; ks < 2; ks++) {
            uint32_t ahf[2][4], whf[4][4];
#pragma unroll
            for (int mt = 0; mt < 2; mt++) {
                uint32_t ao = (wm * 32 + mt * 16 + lr) * RSB + ks * 32 + lh;
                ldsm_x4(ahf[mt], base + ao);
            }
#pragma unroll
            for (int g = 0; g < 4; g++) {
                uint32_t wo = (wn * 64 + g * 16 + lr) * RSB + ks * 32 + lh;
                ldsm_x4(whf[g], base + APART + wo);
            }
#pragma unroll
            for (int mt = 0; mt < 2; mt++)
#pragma unroll
                for (int g = 0; g < 4; g++) {
                    mma16816(acc[mt][2 * g],     ahf[mt], whf[g][0], whf[g][2]);
                    mma16816(acc[mt][2 * g + 1], ahf[mt], whf[g][1], whf[g][3]);
                }
        }
    };

    issue_w(0, 0); CP_COMMIT();
    load_a(0); store_a(0);

    for (int c = 0; c < NCH; c++) {
        CP_WAIT(0);
        __syncthreads();
        if (c + 1 < NCH) {
            issue_w(c + 1, (c + 1) & 1); CP_COMMIT();
            load_a(c + 1);
        }
        compute(c & 1);
        if (c + 1 < NCH) store_a((c + 1) & 1);
    }

    // epilogue: tanh -> single fp16
    const int tq = lane >> 2, tr = lane & 3;
#pragma unroll
    for (int mt = 0; mt < 2; mt++) {
        size_t r0 = arow0 + wm * 32 + mt * 16 + tq;
#pragma unroll
        for (int nt = 0; nt < 8; nt++) {
            int gn = wn * 64 + nt * 8 + tr * 2;
            float bx = __ldg(bias + gn), by = __ldg(bias + gn + 1);
            float v0 = tanhf(acc[mt][nt][0] + bx), v1 = tanhf(acc[mt][nt][1] + by);
            float v2 = tanhf(acc[mt][nt][2] + bx), v3 = tanhf(acc[mt][nt][3] + by);
            *(uint32_t*)(g_enc_h + r0 * DK + gn)       = pack_h2(v0, v1);
            *(uint32_t*)(g_enc_h + (r0 + 8) * DK + gn) = pack_h2(v2, v3);
        }
    }
}

// ===========================================================================
// Fused attention + decode: 256 tokens/block, 512 threads.
// E single fp16 (1-pass logits); P split 2-pass; outputs streaming stores.
// ===========================================================================
#define EROW   528
#define ECROW  144
#define DTROW  1040
#define MEMSZ  (64 * EROW)                 // 33792
#define ECBUF  (256 * ECROW)               // 36864 (single plane)
#define AT_SMEM (MEMSZ + 2 * ECBUF)        // 107520

__global__ void __launch_bounds__(512, 1)
attn_fused(float* __restrict__ att_out, float* __restrict__ mem_out,
           float* __restrict__ recon, const float* __restrict__ dec_b)
{
    extern __shared__ char smc[];
    const uint32_t sb = smem_u32(smc);
    const uint32_t sM = sb;
    const uint32_t sE0 = sb + MEMSZ;
    const uint32_t sD = sE0;              // Dt overlays E buffers after logits

    const int tid = threadIdx.x, wid = tid >> 5, lane = tid & 31;
    const size_t t0 = (size_t)blockIdx.x * 256;

    auto issue_mem = [&]() {
#pragma unroll
        for (int it = 0; it < 4; it++) {
            int idx = tid + it * 512;
            int row = idx >> 5, c = idx & 31;
            cp16(sM + row * EROW + c * 16, g_mem_h + row * DK + c * 8);
        }
    };
    auto issue_e = [&](int kc, int buf) {
        const uint32_t base = sE0 + buf * ECBUF;
#pragma unroll
        for (int it = 0; it < 4; it++) {
            int idx = tid + it * 512;
            int row = idx >> 3, seg = idx & 7;
            cp16(base + row * ECROW + seg * 16,
                 g_enc_h + (t0 + row) * DK + kc * 64 + seg * 8);
        }
    };

    issue_mem();
    issue_e(0, 0);
    CP_COMMIT();

    const int lr = lane & 15, half = lane >> 4;
    const int tq = lane >> 2, tr = lane & 3;
    const int r0 = wid * 16;

    float S[8][4];
#pragma unroll
    for (int i = 0; i < 8; i++)
#pragma unroll
        for (int j = 0; j < 4; j++) S[i][j] = 0.0f;

    for (int kc = 0; kc < 4; kc++) {
        CP_WAIT(0);
        __syncthreads();
        if (kc < 3) { issue_e(kc + 1, (kc + 1) & 1); CP_COMMIT(); }
        const uint32_t eb = sE0 + (kc & 1) * ECBUF;
#pragma unroll
        for (int ks = 0; ks < 4; ks++) {
            uint32_t aoff = (r0 + lr) * ECROW + ks * 32 + half * 16;
            uint32_t ahf[4], bh[4][4];
            ldsm_x4(ahf, eb + aoff);
            const int kbyte = (kc * 4 + ks) * 32 + half * 16;
#pragma unroll
            for (int g = 0; g < 4; g++)
                ldsm_x4(bh[g], sM + (g * 16 + lr) * EROW + kbyte);
#pragma unroll
            for (int g = 0; g < 4; g++) {
                mma16816(S[2 * g],     ahf, bh[g][0], bh[g][2]);
                mma16816(S[2 * g + 1], ahf, bh[g][1], bh[g][3]);
            }
        }
    }

    __syncthreads();

#pragma unroll
    for (int it = 0; it < 8; it++) {
        int idx = tid + it * 512;
        int row = idx >> 6, c = idx & 63;
        cp16(sD + row * DTROW + c * 16, g_dt_h + row * DIN + c * 8);
    }
    CP_COMMIT();

    // softmax (register-only)
    float m0 = -1e30f, m1 = -1e30f;
#pragma unroll
    for (int nt = 0; nt < 8; nt++) {
        m0 = fmaxf(m0, fmaxf(S[nt][0], S[nt][1]));
        m1 = fmaxf(m1, fmaxf(S[nt][2], S[nt][3]));
    }
    m0 = fmaxf(m0, __shfl_xor_sync(0xffffffffu, m0, 1));
    m0 = fmaxf(m0, __shfl_xor_sync(0xffffffffu, m0, 2));
    m1 = fmaxf(m1, __shfl_xor_sync(0xffffffffu, m1, 1));
    m1 = fmaxf(m1, __shfl_xor_sync(0xffffffffu, m1, 2));
    float s0 = 0.0f, s1 = 0.0f;
#pragma unroll
    for (int nt = 0; nt < 8; nt++) {
        S[nt][0] = expf((S[nt][0] - m0) * 0.0625f); s0 += S[nt][0];
        S[nt][1] = expf((S[nt][1] - m0) * 0.0625f); s0 += S[nt][1];
        S[nt][2] = expf((S[nt][2] - m1) * 0.0625f); s1 += S[nt][2];
        S[nt][3] = expf((S[nt][3] - m1) * 0.0625f); s1 += S[nt][3];
    }
    s0 += __shfl_xor_sync(0xffffffffu, s0, 1);
    s0 += __shfl_xor_sync(0xffffffffu, s0, 2);
    s1 += __shfl_xor_sync(0xffffffffu, s1, 1);
    s1 += __shfl_xor_sync(0xffffffffu, s1, 2);
    float i0 = 1.0f / s0, i1 = 1.0f / s1;
#pragma unroll
    for (int nt = 0; nt < 8; nt++) {
        S[nt][0] *= i0; S[nt][1] *= i0; S[nt][2] *= i1; S[nt][3] *= i1;
    }

    uint32_t Ph[4][4], Pl[4][4];
#pragma unroll
    for (int kt = 0; kt < 4; kt++) {
        split2h(S[2 * kt][0],     S[2 * kt][1],     Ph[kt][0], Pl[kt][0]);
        split2h(S[2 * kt][2],     S[2 * kt][3],     Ph[kt][1], Pl[kt][1]);
        split2h(S[2 * kt + 1][0], S[2 * kt + 1][1], Ph[kt][2], Pl[kt][2]);
        split2h(S[2 * kt + 1][2], S[2 * kt + 1][3], Ph[kt][3], Pl[kt][3]);
    }

    const size_t ra = t0 + r0 + tq;
#pragma unroll
    for (int nt = 0; nt < 8; nt++) {
        float2 o0, o1;
        o0.x = S[nt][0]; o0.y = S[nt][1];
        o1.x = S[nt][2]; o1.y = S[nt][3];
        stcs2(att_out + ra * MS + nt * 8 + tr * 2, o0);
        stcs2(att_out + (ra + 8) * MS + nt * 8 + tr * 2, o1);
    }

    // memo = P @ mem (2-pass)
    const int lr8 = lane & 7, kh = (lane >> 3) & 1, nh = lane >> 4;
#pragma unroll
    for (int nc = 0; nc < 4; nc++) {
        float acc2[8][4];
#pragma unroll
        for (int i = 0; i < 8; i++)
#pragma unroll
            for (int j = 0; j < 4; j++) acc2[i][j] = 0.0f;
#pragma unroll
        for (int kt = 0; kt < 4; kt++) {
            uint32_t bh[4][4];
#pragma unroll
            for (int g2 = 0; g2 < 4; g2++) {
                uint32_t boff = (uint32_t)(kt * 16 + kh * 8 + lr8) * EROW +
                                (nc * 64 + g2 * 16 + nh * 8) * 2;
                ldsm_x4_t(bh[g2], sM + boff);
            }
#pragma unroll
            for (int g2 = 0; g2 < 4; g2++) {
                mma16816(acc2[2 * g2],     Ph[kt], bh[g2][0], bh[g2][1]);
                mma16816(acc2[2 * g2 + 1], Ph[kt], bh[g2][2], bh[g2][3]);
            }
#pragma unroll
            for (int g2 = 0; g2 < 4; g2++) {
                mma16816(acc2[2 * g2],     Pl[kt], bh[g2][0], bh[g2][1]);
                mma16816(acc2[2 * g2 + 1], Pl[kt], bh[g2][2], bh[g2][3]);
            }
        }
#pragma unroll
        for (int nt2 = 0; nt2 < 8; nt2++) {
            int gc = nc * 64 + nt2 * 8 + tr * 2;
            float2 o0, o1;
            o0.x = acc2[nt2][0]; o0.y = acc2[nt2][1];
            o1.x = acc2[nt2][2]; o1.y = acc2[nt2][3];
            stcs2(mem_out + ra * DK + gc, o0);
            stcs2(mem_out + (ra + 8) * DK + gc, o1);
        }
    }

    CP_WAIT(0);
    __syncthreads();

    // recon = P @ Dt + dec_b (2-pass)
#pragma unroll
    for (int nc = 0; nc < 8; nc++) {
        float acc2[8][4];
#pragma unroll
        for (int i = 0; i < 8; i++)
#pragma unroll
            for (int j = 0; j < 4; j++) acc2[i][j] = 0.0f;
#pragma unroll
        for (int kt = 0; kt < 4; kt++) {
            uint32_t bh[4][4];
#pragma unroll
            for (int g2 = 0; g2 < 4; g2++) {
                uint32_t boff = (uint32_t)(kt * 16 + kh * 8 + lr8) * DTROW +
                                (nc * 64 + g2 * 16 + nh * 8) * 2;
                ldsm_x4_t(bh[g2], sD + boff);
            }
#pragma unroll
            for (int g2 = 0; g2 < 4; g2++) {
                mma16816(acc2[2 * g2],     Ph[kt], bh[g2][0], bh[g2][1]);
                mma16816(acc2[2 * g2 + 1], Ph[kt], bh[g2][2], bh[g2][3]);
            }
#pragma unroll
            for (int g2 = 0; g2 < 4; g2++) {
                mma16816(acc2[2 * g2],     Pl[kt], bh[g2][0], bh[g2][1]);
                mma16816(acc2[2 * g2 + 1], Pl[kt], bh[g2][2], bh[g2][3]);
            }
        }
#pragma unroll
        for (int nt2 = 0; nt2 < 8; nt2++) {
            int gc = nc * 64 + nt2 * 8 + tr * 2;
            float2 b2 = *(const float2*)(dec_b + gc);
            float2 o0, o1;
            o0.x = acc2[nt2][0] + b2.x; o0.y = acc2[nt2][1] + b2.y;
            o1.x = acc2[nt2][2] + b2.x; o1.y = acc2[nt2][3] + b2.y;
            stcs2(recon + ra * DIN + gc, o0);
            stcs2(recon + (ra + 8) * DIN + gc, o1);
        }
    }
}

// ---------------------------------------------------------------------------
extern "C" void kernel_launch(void* const* d_in, const int* in_sizes, int n_in,
                              void* d_out, int out_size)
{
    const float* seq   = (const float*)d_in[0];
    const float* enc_w = (const float*)d_in[1];
    const float* enc_b = (const float*)d_in[2];
    const float* mem   = (const float*)d_in[3];
    const float* dec_w = (const float*)d_in[4];
    const float* dec_b = (const float*)d_in[5];

    float* recon = (float*)d_out;
    float* att   = recon + (size_t)NTOK * DIN;
    float* memo  = att   + (size_t)NTOK * MS;

    cudaFuncSetAttribute(enc_gemm,
                         cudaFuncAttributeMaxDynamicSharedMemorySize, GEMM_SMEM);
    cudaFuncSetAttribute(attn_fused,
                         cudaFuncAttributeMaxDynamicSharedMemorySize, AT_SMEM);

    prep_cvt<<<DK * DIN / 2 / 256, 256>>>(enc_w, mem);
    prep_dt<<<DIN / 4, 256>>>(dec_w, mem);

    enc_gemm<<<NTOK / 128, 512, GEMM_SMEM>>>(seq, enc_b);

    attn_fused<<<NTOK / 256, 512, AT_SMEM>>>(att, memo, recon, dec_b);
}

// round 15
// speedup vs baseline: 1.4375x; 1.0006x over previous
#include <cuda_runtime.h>
#include <cuda_fp16.h>
#include <cstdint>
#include <math.h>

#define NTOK  65536
#define DIN   512
#define DK    256
#define MS    64

// ---------------- static scratch (fp16) ----------------
__device__ __half g_encw_h[DK * DIN];
__device__ __half g_mem_h[MS * DK];
__device__ __half g_dt_h[MS * DIN];
__device__ __half g_enc_h[(size_t)NTOK * DK];

// ======================= helpers =======================
__device__ __forceinline__ uint32_t smem_u32(const void* p) {
    uint32_t a;
    asm("{ .reg .u64 t; cvta.to.shared.u64 t, %1; cvt.u32.u64 %0, t; }"
        : "=r"(a) : "l"(p));
    return a;
}
__device__ __forceinline__ uint32_t pack_h2(float a, float b) {
    __half2 t = __floats2half2_rn(a, b);
    return *reinterpret_cast<uint32_t*>(&t);
}
__device__ __forceinline__ void split2h(float a, float b, uint32_t& hi, uint32_t& lo) {
    __half ha = __float2half_rn(a), hb = __float2half_rn(b);
    __half2 hp; hp.x = ha; hp.y = hb;
    hi = *reinterpret_cast<uint32_t*>(&hp);
    lo = pack_h2(a - __half2float(ha), b - __half2float(hb));
}
__device__ __forceinline__ void sts64(uint32_t addr, unsigned long long v) {
    asm volatile("st.shared.b64 [%0], %1;" :: "r"(addr), "l"(v) : "memory");
}
__device__ __forceinline__ void cp16(uint32_t saddr, const void* g) {
    asm volatile("cp.async.cg.shared.global [%0], [%1], 16;"
                 :: "r"(saddr), "l"(g) : "memory");
}
#define CP_COMMIT() asm volatile("cp.async.commit_group;" ::: "memory")
#define CP_WAIT(n)  asm volatile("cp.async.wait_group %0;" :: "n"(n) : "memory")

__device__ __forceinline__ void ldsm_x4(uint32_t* r, uint32_t addr) {
    asm volatile("ldmatrix.sync.aligned.m8n8.x4.shared.b16 {%0,%1,%2,%3}, [%4];"
                 : "=r"(r[0]), "=r"(r[1]), "=r"(r[2]), "=r"(r[3]) : "r"(addr));
}
__device__ __forceinline__ void ldsm_x4_t(uint32_t* r, uint32_t addr) {
    asm volatile("ldmatrix.sync.aligned.m8n8.x4.trans.shared.b16 {%0,%1,%2,%3}, [%4];"
                 : "=r"(r[0]), "=r"(r[1]), "=r"(r[2]), "=r"(r[3]) : "r"(addr));
}
__device__ __forceinline__ void mma16816(float* d, const uint32_t* a,
                                         uint32_t b0, uint32_t b1) {
    asm volatile(
        "mma.sync.aligned.m16n8k16.row.col.f32.f16.f16.f32 "
        "{%0,%1,%2,%3}, {%4,%5,%6,%7}, {%8,%9}, {%0,%1,%2,%3};"
        : "+f"(d[0]), "+f"(d[1]), "+f"(d[2]), "+f"(d[3])
        : "r"(a[0]), "r"(a[1]), "r"(a[2]), "r"(a[3]), "r"(b0), "r"(b1));
}
__device__ __forceinline__ void stcs2(float* p, float2 v) {
    asm volatile("st.global.cs.v2.f32 [%0], {%1,%2};" :: "l"(p), "f"(v.x), "f"(v.y)
                 : "memory");
}

// ---------------- prep 1: enc_w, mem -> fp16 ----------------
__global__ void prep_cvt(const float* __restrict__ ew, const float* __restrict__ mm)
{
    int i = blockIdx.x * blockDim.x + threadIdx.x;
    {
        float2 v = __ldg((const float2*)ew + i);
        *((uint32_t*)g_encw_h + i) = pack_h2(v.x, v.y);
    }
    if (i < MS * DK / 2) {
        float2 v = __ldg((const float2*)mm + i);
        *((uint32_t*)g_mem_h + i) = pack_h2(v.x, v.y);
    }
}

// ---------------- prep 2: Dt[s][n] = dec_w[n,:].mem[s,:] -> fp16 ----------------
__global__ void prep_dt(const float* __restrict__ dw, const float* __restrict__ mm)
{
    int s = threadIdx.x & 63;
    int n = blockIdx.x * 4 + (threadIdx.x >> 6);
    const float4* wr = (const float4*)(dw + (size_t)n * DK);
    const float4* mr = (const float4*)(mm + (size_t)s * DK);
    float acc = 0.0f;
#pragma unroll 8
    for (int k = 0; k < DK / 4; k++) {
        float4 a = __ldg(wr + k), b = __ldg(mr + k);
        acc += a.x * b.x + a.y * b.y + a.z * b.z + a.w * b.w;
    }
    g_dt_h[s * DIN + n] = __float2half_rn(acc);
}

// ===========================================================================
// Encode GEMM: BM=128, BN=128, BK=32, 256 threads, 2 CTAs/SM.
// Warp grid 4(M)x2(N), warp tile 32x64. Single fp16, 1-pass MMA.
// ===========================================================================
#define RSB    80
#define APART  (128 * RSB)                 // 10240
#define WPART  (128 * RSB)                 // 10240
#define BUFSZ  (APART + WPART)             // 20480
#define GEMM_SMEM (2 * BUFSZ)              // 40960

__global__ void __launch_bounds__(256, 2)
enc_gemm(const float* __restrict__ A32, const float* __restrict__ bias)
{
    extern __shared__ char smc[];
    const uint32_t sb = smem_u32(smc);
    const int tid = threadIdx.x, wid = tid >> 5, lane = tid & 31;
    const int wm = wid & 3, wn = wid >> 2;     // 4x2 warp grid, 32x64 tiles
    const int NCH = DIN / 32;                  // 16

    const size_t arow0 = (size_t)blockIdx.y * 128;
    const int n0 = blockIdx.x * 128;

    float acc[2][8][4];
#pragma unroll
    for (int i = 0; i < 2; i++)
#pragma unroll
        for (int j = 0; j < 8; j++)
#pragma unroll
            for (int k = 0; k < 4; k++) acc[i][j][k] = 0.0f;

    float4 av[4];

    auto issue_w = [&](int c, int buf) {
        const uint32_t base = sb + buf * BUFSZ + APART;
        // 128 rows x 4 x 16B segments = 512 cp16, 2 per thread
#pragma unroll
        for (int l = 0; l < 2; l++) {
            int idx = tid + l * 256;
            int row = idx >> 2, seg = idx & 3;
            cp16(base + row * RSB + seg * 16,
                 g_encw_h + (size_t)(n0 + row) * DIN + c * 32 + seg * 8);
        }
    };
    auto load_a = [&](int c) {
#pragma unroll
        for (int l = 0; l < 4; l++) {
            int idx = tid + l * 256;
            int row = idx >> 3, q = idx & 7;
            av[l] = __ldg((const float4*)(A32 + (arow0 + row) * DIN + c * 32 + q * 4));
        }
    };
    auto store_a = [&](int buf) {
        const uint32_t base = sb + buf * BUFSZ;
#pragma unroll
        for (int l = 0; l < 4; l++) {
            int idx = tid + l * 256;
            int row = idx >> 3, q = idx & 7;
            unsigned long long h =
                (unsigned long long)pack_h2(av[l].x, av[l].y) |
                ((unsigned long long)pack_h2(av[l].z, av[l].w) << 32);
            sts64(base + row * RSB + q * 8, h);
        }
    };
    auto compute = [&](int buf) {
        const uint32_t base = sb + buf * BUFSZ;
        const uint32_t lr = lane & 15, lh = (lane >> 4) * 16;
#pragma unroll
        for (int ks = 0; ks < 2; ks++) {
            uint32_t ahf[2][4], whf[4][4];
#pragma unroll
            for (int mt = 0; mt < 2; mt++) {
                uint32_t ao = (wm * 32 + mt * 16 + lr) * RSB + ks * 32 + lh;
                ldsm_x4(ahf[mt], base + ao);
            }
#pragma unroll
            for (int g = 0; g < 4; g++) {
                uint32_t wo = (wn * 64 + g * 16 + lr) * RSB + ks * 32 + lh;
                ldsm_x4(whf[g], base + APART + wo);
            }
#pragma unroll
            for (int mt = 0; mt < 2; mt++)
#pragma unroll
                for (int g = 0; g < 4; g++) {
                    mma16816(acc[mt][2 * g],     ahf[mt], whf[g][0], whf[g][2]);
                    mma16816(acc[mt][2 * g + 1], ahf[mt], whf[g][1], whf[g][3]);
                }
        }
    };

    issue_w(0, 0); CP_COMMIT();
    load_a(0); store_a(0);

    for (int c = 0; c < NCH; c++) {
        CP_WAIT(0);
        __syncthreads();
        if (c + 1 < NCH) {
            issue_w(c + 1, (c + 1) & 1); CP_COMMIT();
            load_a(c + 1);
        }
        compute(c & 1);
        if (c + 1 < NCH) store_a((c + 1) & 1);
    }

    // epilogue: tanh -> single fp16
    const int tq = lane >> 2, tr = lane & 3;
#pragma unroll
    for (int mt = 0; mt < 2; mt++) {
        size_t r0 = arow0 + wm * 32 + mt * 16 + tq;
#pragma unroll
        for (int nt = 0; nt < 8; nt++) {
            int gn = n0 + wn * 64 + nt * 8 + tr * 2;
            float bx = __ldg(bias + gn), by = __ldg(bias + gn + 1);
            float v0 = tanhf(acc[mt][nt][0] + bx), v1 = tanhf(acc[mt][nt][1] + by);
            float v2 = tanhf(acc[mt][nt][2] + bx), v3 = tanhf(acc[mt][nt][3] + by);
            *(uint32_t*)(g_enc_h + r0 * DK + gn)       = pack_h2(v0, v1);
            *(uint32_t*)(g_enc_h + (r0 + 8) * DK + gn) = pack_h2(v2, v3);
        }
    }
}

// ===========================================================================
// Fused attention + decode: 128 tokens/block, 256 threads, 2 CTAs/SM.
// ===========================================================================
#define EROW   528
#define ECROW  144
#define DTROW  1040
#define MEMSZ  (64 * EROW)                 // 33792
#define ECBUF  (128 * ECROW)               // 18432 per chunk buffer
#define DTSZ   (64 * DTROW)                // 66560
#define AT_SMEM (MEMSZ + DTSZ)             // 100352

__global__ void __launch_bounds__(256, 2)
attn_fused(float* __restrict__ att_out, float* __restrict__ mem_out,
           float* __restrict__ recon, const float* __restrict__ dec_b)
{
    extern __shared__ char smc[];
    const uint32_t sb = smem_u32(smc);
    const uint32_t sM = sb;
    const uint32_t sE0 = sb + MEMSZ;
    const uint32_t sD = sE0;

    const int tid = threadIdx.x, wid = tid >> 5, lane = tid & 31;
    const size_t t0 = (size_t)blockIdx.x * 128;

    auto issue_mem = [&]() {
#pragma unroll
        for (int it = 0; it < 8; it++) {
            int idx = tid + it * 256;
            int row = idx >> 5, c = idx & 31;
            cp16(sM + row * EROW + c * 16, g_mem_h + row * DK + c * 8);
        }
    };
    auto issue_e = [&](int kc, int buf) {
        const uint32_t base = sE0 + buf * ECBUF;
#pragma unroll
        for (int it = 0; it < 4; it++) {
            int idx = tid + it * 256;
            int row = idx >> 3, seg = idx & 7;
            cp16(base + row * ECROW + seg * 16,
                 g_enc_h + (t0 + row) * DK + kc * 64 + seg * 8);
        }
    };

    issue_mem();
    issue_e(0, 0);
    CP_COMMIT();

    const int lr = lane & 15, half = lane >> 4;
    const int tq = lane >> 2, tr = lane & 3;
    const int r0 = wid * 16;

    float S[8][4];
#pragma unroll
    for (int i = 0; i < 8; i++)
#pragma unroll
        for (int j = 0; j < 4; j++) S[i][j] = 0.0f;

    for (int kc = 0; kc < 4; kc++) {
        CP_WAIT(0);
        __syncthreads();
        if (kc < 3) { issue_e(kc + 1, (kc + 1) & 1); CP_COMMIT(); }
        const uint32_t eb = sE0 + (kc & 1) * ECBUF;
#pragma unroll
        for (int ks = 0; ks < 4; ks++) {
            uint32_t aoff = (r0 + lr) * ECROW + ks * 32 + half * 16;
            uint32_t ahf[4], bh[4][4];
            ldsm_x4(ahf, eb + aoff);
            const int kbyte = (kc * 4 + ks) * 32 + half * 16;
#pragma unroll
            for (int g = 0; g < 4; g++)
                ldsm_x4(bh[g], sM + (g * 16 + lr) * EROW + kbyte);
#pragma unroll
            for (int g = 0; g < 4; g++) {
                mma16816(S[2 * g],     ahf, bh[g][0], bh[g][2]);
                mma16816(S[2 * g + 1], ahf, bh[g][1], bh[g][3]);
            }
        }
    }

    __syncthreads();

    // prefetch Dt over E region
#pragma unroll
    for (int it = 0; it < 16; it++) {
        int idx = tid + it * 256;
        int row = idx >> 6, c = idx & 63;
        cp16(sD + row * DTROW + c * 16, g_dt_h + row * DIN + c * 8);
    }
    CP_COMMIT();

    // softmax (register-only)
    float m0 = -1e30f, m1 = -1e30f;
#pragma unroll
    for (int nt = 0; nt < 8; nt++) {
        m0 = fmaxf(m0, fmaxf(S[nt][0], S[nt][1]));
        m1 = fmaxf(m1, fmaxf(S[nt][2], S[nt][3]));
    }
    m0 = fmaxf(m0, __shfl_xor_sync(0xffffffffu, m0, 1));
    m0 = fmaxf(m0, __shfl_xor_sync(0xffffffffu, m0, 2));
    m1 = fmaxf(m1, __shfl_xor_sync(0xffffffffu, m1, 1));
    m1 = fmaxf(m1, __shfl_xor_sync(0xffffffffu, m1, 2));
    float s0 = 0.0f, s1 = 0.0f;
#pragma unroll
    for (int nt = 0; nt < 8; nt++) {
        S[nt][0] = expf((S[nt][0] - m0) * 0.0625f); s0 += S[nt][0];
        S[nt][1] = expf((S[nt][1] - m0) * 0.0625f); s0 += S[nt][1];
        S[nt][2] = expf((S[nt][2] - m1) * 0.0625f); s1 += S[nt][2];
        S[nt][3] = expf((S[nt][3] - m1) * 0.0625f); s1 += S[nt][3];
    }
    s0 += __shfl_xor_sync(0xffffffffu, s0, 1);
    s0 += __shfl_xor_sync(0xffffffffu, s0, 2);
    s1 += __shfl_xor_sync(0xffffffffu, s1, 1);
    s1 += __shfl_xor_sync(0xffffffffu, s1, 2);
    float i0 = 1.0f / s0, i1 = 1.0f / s1;
#pragma unroll
    for (int nt = 0; nt < 8; nt++) {
        S[nt][0] *= i0; S[nt][1] *= i0; S[nt][2] *= i1; S[nt][3] *= i1;
    }

    uint32_t Ph[4][4], Pl[4][4];
#pragma unroll
    for (int kt = 0; kt < 4; kt++) {
        split2h(S[2 * kt][0],     S[2 * kt][1],     Ph[kt][0], Pl[kt][0]);
        split2h(S[2 * kt][2],     S[2 * kt][3],     Ph[kt][1], Pl[kt][1]);
        split2h(S[2 * kt + 1][0], S[2 * kt + 1][1], Ph[kt][2], Pl[kt][2]);
        split2h(S[2 * kt + 1][2], S[2 * kt + 1][3], Ph[kt][3], Pl[kt][3]);
    }

    const size_t ra = t0 + r0 + tq;
#pragma unroll
    for (int nt = 0; nt < 8; nt++) {
        float2 o0, o1;
        o0.x = S[nt][0]; o0.y = S[nt][1];
        o1.x = S[nt][2]; o1.y = S[nt][3];
        stcs2(att_out + ra * MS + nt * 8 + tr * 2, o0);
        stcs2(att_out + (ra + 8) * MS + nt * 8 + tr * 2, o1);
    }

    // memo = P @ mem (2-pass)
    const int lr8 = lane & 7, kh = (lane >> 3) & 1, nh = lane >> 4;
#pragma unroll
    for (int nc = 0; nc < 4; nc++) {
        float acc2[8][4];
#pragma unroll
        for (int i = 0; i < 8; i++)
#pragma unroll
            for (int j = 0; j < 4; j++) acc2[i][j] = 0.0f;
#pragma unroll
        for (int kt = 0; kt < 4; kt++) {
            uint32_t bh[4][4];
#pragma unroll
            for (int g2 = 0; g2 < 4; g2++) {
                uint32_t boff = (uint32_t)(kt * 16 + kh * 8 + lr8) * EROW +
                                (nc * 64 + g2 * 16 + nh * 8) * 2;
                ldsm_x4_t(bh[g2], sM + boff);
            }
#pragma unroll
            for (int g2 = 0; g2 < 4; g2++) {
                mma16816(acc2[2 * g2],     Ph[kt], bh[g2][0], bh[g2][1]);
                mma16816(acc2[2 * g2 + 1], Ph[kt], bh[g2][2], bh[g2][3]);
            }
#pragma unroll
            for (int g2 = 0; g2 < 4; g2++) {
                mma16816(acc2[2 * g2],     Pl[kt], bh[g2][0], bh[g2][1]);
                mma16816(acc2[2 * g2 + 1], Pl[kt], bh[g2][2], bh[g2][3]);
            }
        }
#pragma unroll
        for (int nt2 = 0; nt2 < 8; nt2++) {
            int gc = nc * 64 + nt2 * 8 + tr * 2;
            float2 o0, o1;
            o0.x = acc2[nt2][0]; o0.y = acc2[nt2][1];
            o1.x = acc2[nt2][2]; o1.y = acc2[nt2][3];
            stcs2(mem_out + ra * DK + gc, o0);
            stcs2(mem_out + (ra + 8) * DK + gc, o1);
        }
    }

    CP_WAIT(0);
    __syncthreads();

    // recon = P @ Dt + dec_b (2-pass)
#pragma unroll
    for (int nc = 0; nc < 8; nc++) {
        float acc2[8][4];
#pragma unroll
        for (int i = 0; i < 8; i++)
#pragma unroll
            for (int j = 0; j < 4; j++) acc2[i][j] = 0.0f;
#pragma unroll
        for (int kt = 0; kt < 4; kt++) {
            uint32_t bh[4][4];
#pragma unroll
            for (int g2 = 0; g2 < 4; g2++) {
                uint32_t boff = (uint32_t)(kt * 16 + kh * 8 + lr8) * DTROW +
                                (nc * 64 + g2 * 16 + nh * 8) * 2;
                ldsm_x4_t(bh[g2], sD + boff);
            }
#pragma unroll
            for (int g2 = 0; g2 < 4; g2++) {
                mma16816(acc2[2 * g2],     Ph[kt], bh[g2][0], bh[g2][1]);
                mma16816(acc2[2 * g2 + 1], Ph[kt], bh[g2][2], bh[g2][3]);
            }
#pragma unroll
            for (int g2 = 0; g2 < 4; g2++) {
                mma16816(acc2[2 * g2],     Pl[kt], bh[g2][0], bh[g2][1]);
                mma16816(acc2[2 * g2 + 1], Pl[kt], bh[g2][2], bh[g2][3]);
            }
        }
#pragma unroll
        for (int nt2 = 0; nt2 < 8; nt2++) {
            int gc = nc * 64 + nt2 * 8 + tr * 2;
            float2 b2 = *(const float2*)(dec_b + gc);
            float2 o0, o1;
            o0.x = acc2[nt2][0] + b2.x; o0.y = acc2[nt2][1] + b2.y;
            o1.x = acc2[nt2][2] + b2.x; o1.y = acc2[nt2][3] + b2.y;
            stcs2(recon + ra * DIN + gc, o0);
            stcs2(recon + (ra + 8) * DIN + gc, o1);
        }
    }
}

// ---------------------------------------------------------------------------
extern "C" void kernel_launch(void* const* d_in, const int* in_sizes, int n_in,
                              void* d_out, int out_size)
{
    const float* seq   = (const float*)d_in[0];
    const float* enc_w = (const float*)d_in[1];
    const float* enc_b = (const float*)d_in[2];
    const float* mem   = (const float*)d_in[3];
    const float* dec_w = (const float*)d_in[4];
    const float* dec_b = (const float*)d_in[5];

    float* recon = (float*)d_out;
    float* att   = recon + (size_t)NTOK * DIN;
    float* memo  = att   + (size_t)NTOK * MS;

    cudaFuncSetAttribute(enc_gemm,
                         cudaFuncAttributeMaxDynamicSharedMemorySize, GEMM_SMEM);
    cudaFuncSetAttribute(attn_fused,
                         cudaFuncAttributeMaxDynamicSharedMemorySize, AT_SMEM);

    prep_cvt<<<DK * DIN / 2 / 256, 256>>>(enc_w, mem);
    prep_dt<<<DIN / 4, 256>>>(dec_w, mem);

    dim3 g1(2, NTOK / 128);      // N fastest -> seq tiles L2-hot across N pair
    enc_gemm<<<g1, 256, GEMM_SMEM>>>(seq, enc_b);

    attn_fused<<<NTOK / 128, 256, AT_SMEM>>>(att, memo, recon, dec_b);
}